// round 1
// baseline (speedup 1.0000x reference)
#include <cuda_runtime.h>

#define NI      1022      // interior size (N-2)
#define NF      1024      // full size N
#define PITCH   1024      // padded row pitch for internal buffers (128B aligned)
#define BATCH   8
#define NSTEPS  11        // 1 initial step + MAXITER(10) scan steps

// Scratch (allocation-free rule: __device__ globals)
__device__ float g_bufA[BATCH * NI * PITCH];
__device__ float g_bufB[BATCH * NI * PITCH];
__device__ float g_force[BATCH * NI * PITCH];
__device__ float g_coef[9];   // (k1+k2)/sum(k3)
__device__ float g_cf[1];     // H^2 / (mu * sum(k3))

// --- tiny setup: fold mu/k1/k2/k3 into 10 scalars ---------------------------
__global__ void setup_coef_kernel(const float* __restrict__ mu,
                                  const float* __restrict__ k1,
                                  const float* __restrict__ k2,
                                  const float* __restrict__ k3) {
    float s3 = 0.0f;
    #pragma unroll
    for (int i = 0; i < 9; i++) s3 += k3[i];
    float inv = 1.0f / s3;
    #pragma unroll
    for (int i = 0; i < 9; i++) g_coef[i] = (k1[i] + k2[i]) * inv;
    const float Hval = 1.0f / (float)(NF - 1);
    g_cf[0] = Hval * Hval / (mu[0] * s3);
}

// --- precompute force = f_interior * H^2 / (mu*S3) into pitch-1024 buffer ---
__global__ void force_kernel(const float* __restrict__ f) {
    int gx = blockIdx.x * blockDim.x + threadIdx.x;
    int gy = blockIdx.y * blockDim.y + threadIdx.y;
    int b  = blockIdx.z;
    if (gx >= NI || gy >= NI) return;
    float cf = g_cf[0];
    g_force[((size_t)b * NI + gy) * PITCH + gx] =
        f[((size_t)b * NF + (gy + 1)) * NF + (gx + 1)] * cf;
}

// --- one Jacobi step: out = force + sum(coef * zero-padded neighbors) -------
__global__ void step_kernel(const float* __restrict__ in, int in_pitch,
                            float* __restrict__ out, int out_pitch) {
    int gx = blockIdx.x * blockDim.x + threadIdx.x;
    int gy = blockIdx.y * blockDim.y + threadIdx.y;
    int b  = blockIdx.z;
    if (gx >= NI || gy >= NI) return;

    float c0 = g_coef[0], c1 = g_coef[1], c2 = g_coef[2];
    float c3 = g_coef[3], c4 = g_coef[4], c5 = g_coef[5];
    float c6 = g_coef[6], c7 = g_coef[7], c8 = g_coef[8];

    const float* src = in + (size_t)b * NI * in_pitch;
    float acc = g_force[((size_t)b * NI + gy) * PITCH + gx];

    bool xlo = (gx > 0);
    bool xhi = (gx < NI - 1);

    if (gy > 0) {
        const float* r = src + (size_t)(gy - 1) * in_pitch;
        if (xlo) acc += c0 * r[gx - 1];
        acc += c1 * r[gx];
        if (xhi) acc += c2 * r[gx + 1];
    }
    {
        const float* r = src + (size_t)gy * in_pitch;
        if (xlo) acc += c3 * r[gx - 1];
        acc += c4 * r[gx];
        if (xhi) acc += c5 * r[gx + 1];
    }
    if (gy < NI - 1) {
        const float* r = src + (size_t)(gy + 1) * in_pitch;
        if (xlo) acc += c6 * r[gx - 1];
        acc += c7 * r[gx];
        if (xhi) acc += c8 * r[gx + 1];
    }

    out[((size_t)b * NI + gy) * out_pitch + gx] = acc;
}

extern "C" void kernel_launch(void* const* d_in, const int* in_sizes, int n_in,
                              void* d_out, int out_size) {
    // metadata order: x, pre, f, mu, k1, k2, k3  (x is unused by the reference)
    const float* pre = (const float*)d_in[1];
    const float* f   = (const float*)d_in[2];
    const float* mu  = (const float*)d_in[3];
    const float* k1  = (const float*)d_in[4];
    const float* k2  = (const float*)d_in[5];
    const float* k3  = (const float*)d_in[6];
    float* out = (float*)d_out;

    void *pA = nullptr, *pB = nullptr;
    cudaGetSymbolAddress(&pA, g_bufA);
    cudaGetSymbolAddress(&pB, g_bufB);

    setup_coef_kernel<<<1, 1>>>(mu, k1, k2, k3);

    dim3 blk(128, 4, 1);
    dim3 grd((NI + blk.x - 1) / blk.x, (NI + blk.y - 1) / blk.y, BATCH);

    force_kernel<<<grd, blk>>>(f);

    // step 0: pre (pitch 1022) -> bufA (pitch 1024)
    step_kernel<<<grd, blk>>>(pre, NI, (float*)pA, PITCH);

    // steps 1..9: ping-pong A <-> B (pitch 1024)
    const float* cur = (const float*)pA;
    float*       nxt = (float*)pB;
    for (int it = 1; it <= NSTEPS - 2; it++) {
        step_kernel<<<grd, blk>>>(cur, PITCH, nxt, PITCH);
        const float* t = cur; cur = nxt; nxt = (float*)t;
    }

    // final step 10: -> d_out (pitch 1022, compact layout)
    step_kernel<<<grd, blk>>>(cur, PITCH, out, NI);
}

// round 2
// speedup vs baseline: 3.0293x; 3.0293x over previous
#include <cuda_runtime.h>

#define NI      1022      // interior size (N-2)
#define NF      1024      // full size N
#define PITCH   1024      // padded row pitch (128B aligned)
#define BATCH   8
#define NSTEPS  11        // 1 initial step + 10 scan steps
#define ROWS    8         // output rows per thread
#define TY      4         // thread rows per block

__device__ float g_bufA[BATCH * NI * PITCH];
__device__ float g_bufB[BATCH * NI * PITCH];
__device__ float g_force[BATCH * NI * PITCH];
__device__ float g_coef[9];
__device__ float g_cf[1];

__constant__ float c_coef[9];

// --- fold mu/k1/k2/k3 into 10 scalars ---------------------------------------
__global__ void setup_coef_kernel(const float* __restrict__ mu,
                                  const float* __restrict__ k1,
                                  const float* __restrict__ k2,
                                  const float* __restrict__ k3) {
    float s3 = 0.0f;
    #pragma unroll
    for (int i = 0; i < 9; i++) s3 += k3[i];
    float inv = 1.0f / s3;
    #pragma unroll
    for (int i = 0; i < 9; i++) g_coef[i] = (k1[i] + k2[i]) * inv;
    const float Hval = 1.0f / (float)(NF - 1);
    g_cf[0] = Hval * Hval / (mu[0] * s3);
}

// --- force = f_interior * H^2/(mu*S3), pitch-1024, padding stays zero -------
__global__ void force_kernel(const float* __restrict__ f) {
    int x0 = (blockIdx.x * blockDim.x + threadIdx.x) * 4;
    int y  = blockIdx.y;
    int b  = blockIdx.z;
    if (x0 >= NI + 2) return;   // cover up to col 1021
    float cf = g_cf[0];
    const float* frow = f + ((size_t)b * NF + (y + 1)) * NF;
    // need f cols x0+1 .. x0+4
    float4 q0 = *(const float4*)(frow + x0);
    float v1 = q0.y, v2 = q0.z, v3 = q0.w;
    float v4 = (x0 + 4 < NF) ? frow[x0 + 4] : 0.0f;
    float* orow = g_force + ((size_t)b * NI + y) * PITCH;
    if (x0 + 3 < NI) {
        float4 o; o.x = v1 * cf; o.y = v2 * cf; o.z = v3 * cf; o.w = v4 * cf;
        *(float4*)(orow + x0) = o;
    } else {
        if (x0 + 0 < NI) orow[x0 + 0] = v1 * cf;
        if (x0 + 1 < NI) orow[x0 + 1] = v2 * cf;
        if (x0 + 2 < NI) orow[x0 + 2] = v3 * cf;
        if (x0 + 3 < NI) orow[x0 + 3] = v4 * cf;
    }
}

// --- fused horizontal conv helper -------------------------------------------
__device__ __forceinline__ float4 hconv(float cA, float cB, float cC,
                                        float l, float4 v, float r) {
    float4 h;
    h.x = cA * l   + cB * v.x + cC * v.y;
    h.y = cA * v.x + cB * v.y + cC * v.z;
    h.z = cA * v.y + cB * v.z + cC * v.w;
    h.w = cA * v.z + cB * v.w + cC * r;
    return h;
}

// --- one Jacobi step, vectorized + register-rolled --------------------------
// VEC_IN:  input is pitch-1024 with zero padding cols -> float4 + shuffle path
// VEC_OUT: output is pitch-1024 -> float4 stores (masked at right edge)
template<bool VEC_IN, bool VEC_OUT>
__global__ void __launch_bounds__(32 * TY)
step_kernel(const float* __restrict__ in, int in_pitch,
            float* __restrict__ out, int out_pitch) {
    const unsigned FULL = 0xffffffffu;
    int lane  = threadIdx.x;                       // 0..31
    int x0    = (blockIdx.x * 32 + lane) * 4;      // col of v.x
    int ybase = (blockIdx.y * TY + threadIdx.y) * ROWS;
    int b     = blockIdx.z;

    if (ybase >= NI) return;

    float c0 = c_coef[0], c1 = c_coef[1], c2 = c_coef[2];
    float c3 = c_coef[3], c4 = c_coef[4], c5 = c_coef[5];
    float c6 = c_coef[6], c7 = c_coef[7], c8 = c_coef[8];

    const float* src = in + (size_t)b * NI * in_pitch;

    float4 acc[ROWS];
    #pragma unroll
    for (int i = 0; i < ROWS; i++) {
        int row = ybase + i;
        if (row < NI) {
            acc[i] = *(const float4*)(g_force + ((size_t)b * NI + row) * PITCH + x0);
        } else {
            acc[i].x = acc[i].y = acc[i].z = acc[i].w = 0.0f;
        }
    }

    #pragma unroll
    for (int rj = 0; rj <= ROWS + 1; rj++) {
        int ri  = rj - 1;           // -1 .. ROWS
        int row = ybase + ri;
        if (row < 0 || row >= NI) continue;

        const float* rp = src + (size_t)row * in_pitch;
        float4 v; float l, rr;
        if (VEC_IN) {
            v = *(const float4*)(rp + x0);
            l  = __shfl_up_sync(FULL, v.w, 1);
            if (lane == 0)  l  = (x0 > 0)        ? rp[x0 - 1] : 0.0f;
            rr = __shfl_down_sync(FULL, v.x, 1);
            if (lane == 31) rr = (x0 + 4 < NI)   ? rp[x0 + 4] : 0.0f;
        } else {
            l   = (x0 - 1 >= 0 && x0 - 1 < NI) ? rp[x0 - 1] : 0.0f;
            v.x = (x0 + 0 < NI) ? rp[x0 + 0] : 0.0f;
            v.y = (x0 + 1 < NI) ? rp[x0 + 1] : 0.0f;
            v.z = (x0 + 2 < NI) ? rp[x0 + 2] : 0.0f;
            v.w = (x0 + 3 < NI) ? rp[x0 + 3] : 0.0f;
            rr  = (x0 + 4 < NI) ? rp[x0 + 4] : 0.0f;
        }

        // this row contributes: as TOP (c0..c2) to output ri+1,
        // as MID (c3..c5) to output ri, as BOT (c6..c8) to output ri-1
        if (ri + 1 >= 0 && ri + 1 < ROWS) {
            float4 h = hconv(c0, c1, c2, l, v, rr);
            acc[ri + 1].x += h.x; acc[ri + 1].y += h.y;
            acc[ri + 1].z += h.z; acc[ri + 1].w += h.w;
        }
        if (ri >= 0 && ri < ROWS) {
            float4 h = hconv(c3, c4, c5, l, v, rr);
            acc[ri].x += h.x; acc[ri].y += h.y;
            acc[ri].z += h.z; acc[ri].w += h.w;
        }
        if (ri - 1 >= 0 && ri - 1 < ROWS) {
            float4 h = hconv(c6, c7, c8, l, v, rr);
            acc[ri - 1].x += h.x; acc[ri - 1].y += h.y;
            acc[ri - 1].z += h.z; acc[ri - 1].w += h.w;
        }
    }

    #pragma unroll
    for (int i = 0; i < ROWS; i++) {
        int row = ybase + i;
        if (row >= NI) continue;
        float* orow = out + ((size_t)b * NI + row) * out_pitch;
        if (VEC_OUT) {
            if (x0 + 3 < NI) {
                *(float4*)(orow + x0) = acc[i];
            } else {
                if (x0 + 0 < NI) orow[x0 + 0] = acc[i].x;
                if (x0 + 1 < NI) orow[x0 + 1] = acc[i].y;
                // x0+2 >= 1022 at the edge; padding must stay zero -> skip
            }
        } else {
            if (x0 + 0 < NI) orow[x0 + 0] = acc[i].x;
            if (x0 + 1 < NI) orow[x0 + 1] = acc[i].y;
            if (x0 + 2 < NI) orow[x0 + 2] = acc[i].z;
            if (x0 + 3 < NI) orow[x0 + 3] = acc[i].w;
        }
    }
}

extern "C" void kernel_launch(void* const* d_in, const int* in_sizes, int n_in,
                              void* d_out, int out_size) {
    // metadata order: x, pre, f, mu, k1, k2, k3  (x unused by the reference)
    const float* pre = (const float*)d_in[1];
    const float* f   = (const float*)d_in[2];
    const float* mu  = (const float*)d_in[3];
    const float* k1  = (const float*)d_in[4];
    const float* k2  = (const float*)d_in[5];
    const float* k3  = (const float*)d_in[6];
    float* out = (float*)d_out;

    void *pA = nullptr, *pB = nullptr, *pC = nullptr;
    cudaGetSymbolAddress(&pA, g_bufA);
    cudaGetSymbolAddress(&pB, g_bufB);
    cudaGetSymbolAddress(&pC, g_coef);

    setup_coef_kernel<<<1, 1>>>(mu, k1, k2, k3);
    cudaMemcpyToSymbolAsync(c_coef, pC, 9 * sizeof(float), 0,
                            cudaMemcpyDeviceToDevice);

    {   // force precompute
        dim3 blk(128, 1, 1);
        dim3 grd((NF / 4 + 127) / 128, NI, BATCH);
        force_kernel<<<grd, blk>>>(f);
    }

    dim3 blk(32, TY, 1);
    dim3 grd(NF / 128, (NI + TY * ROWS - 1) / (TY * ROWS), BATCH);

    // step 0: pre (compact pitch 1022, scalar loads) -> bufA (pitch 1024)
    step_kernel<false, true><<<grd, blk>>>(pre, NI, (float*)pA, PITCH);

    // steps 1..9: ping-pong A <-> B, fully vectorized
    const float* cur = (const float*)pA;
    float*       nxt = (float*)pB;
    for (int it = 1; it <= NSTEPS - 2; it++) {
        step_kernel<true, true><<<grd, blk>>>(cur, PITCH, nxt, PITCH);
        const float* t = cur; cur = nxt; nxt = (float*)t;
    }

    // final step: -> d_out (compact pitch 1022, scalar stores)
    step_kernel<true, false><<<grd, blk>>>(cur, PITCH, out, NI);
}